// round 7
// baseline (speedup 1.0000x reference)
#include <cuda_runtime.h>
#include <cuda_bf16.h>
#include <cstdint>

#define BDIM 1024
#define KDIM 2048
#define NDIM 4096

// Scratch (device globals — no allocation allowed)
__device__ int8_t g_xq[BDIM * KDIM];          // quantized x [1024][2048]
__device__ int8_t g_wq[NDIM * KDIM];          // quantized protos [4096][2048]
__device__ __nv_bfloat16 g_wb[NDIM * KDIM];   // transposed protos bf16 (intermediate)
__device__ float g_xsq[BDIM];
__device__ float g_psq[NDIM];
__device__ float g_sx2[BDIM];                 // 2 * rowmax/127
__device__ int   g_wmaxi[NDIM];               // per-o max|W| as float bits

// ---------------------------------------------------------------------------
// Kernel 1: zero psq + wmax
// ---------------------------------------------------------------------------
__global__ void zero_k() {
    int i = blockIdx.x * blockDim.x + threadIdx.x;
    if (i < NDIM) { g_psq[i] = 0.0f; g_wmaxi[i] = 0; }
}

// ---------------------------------------------------------------------------
// Kernel 2: x -> int8 (per-row scale), x_sq fp32. 1 block/row, 256 threads.
// ---------------------------------------------------------------------------
__global__ void pack_x_k(const float* __restrict__ x) {
    int row = blockIdx.x;
    int t = threadIdx.x;
    const float4* xr = reinterpret_cast<const float4*>(x + (size_t)row * KDIM);
    float4 v0 = xr[t * 2];
    float4 v1 = xr[t * 2 + 1];

    float s = v0.x*v0.x + v0.y*v0.y + v0.z*v0.z + v0.w*v0.w
            + v1.x*v1.x + v1.y*v1.y + v1.z*v1.z + v1.w*v1.w;
    float m = fmaxf(fmaxf(fmaxf(fabsf(v0.x), fabsf(v0.y)), fmaxf(fabsf(v0.z), fabsf(v0.w))),
                    fmaxf(fmaxf(fabsf(v1.x), fabsf(v1.y)), fmaxf(fabsf(v1.z), fabsf(v1.w))));

    #pragma unroll
    for (int off = 16; off; off >>= 1) {
        s += __shfl_xor_sync(0xffffffffu, s, off);
        m = fmaxf(m, __shfl_xor_sync(0xffffffffu, m, off));
    }
    __shared__ float ws[8], wm[8], binv[1];
    if ((t & 31) == 0) { ws[t >> 5] = s; wm[t >> 5] = m; }
    __syncthreads();
    if (t == 0) {
        float tot = 0.0f, mx = 0.0f;
        #pragma unroll
        for (int j = 0; j < 8; j++) { tot += ws[j]; mx = fmaxf(mx, wm[j]); }
        g_xsq[row] = tot;
        g_sx2[row] = 2.0f * mx * (1.0f / 127.0f);
        binv[0] = 127.0f / mx;
    }
    __syncthreads();
    float inv = binv[0];

    int q[8];
    q[0] = __float2int_rn(v0.x * inv); q[1] = __float2int_rn(v0.y * inv);
    q[2] = __float2int_rn(v0.z * inv); q[3] = __float2int_rn(v0.w * inv);
    q[4] = __float2int_rn(v1.x * inv); q[5] = __float2int_rn(v1.y * inv);
    q[6] = __float2int_rn(v1.z * inv); q[7] = __float2int_rn(v1.w * inv);
    uint2 pk;
    pk.x = (q[0] & 0xFF) | ((q[1] & 0xFF) << 8) | ((q[2] & 0xFF) << 16) | (q[3] << 24);
    pk.y = (q[4] & 0xFF) | ((q[5] & 0xFF) << 8) | ((q[6] & 0xFF) << 16) | (q[7] << 24);
    *reinterpret_cast<uint2*>(g_xq + (size_t)row * KDIM + t * 8) = pk;
}

// ---------------------------------------------------------------------------
// Kernel 3: transpose W [4096,2048] fp32 -> protos bf16 [4096][2048],
// fused p_sq partial sums + per-o |max| (atomicMax on float bits).
// ---------------------------------------------------------------------------
__global__ void pack_w_k(const float* __restrict__ W) {
    __shared__ float tile[32][33];
    __shared__ float sqs[8][32];
    __shared__ float mxs[8][32];

    int c0 = blockIdx.x * 32;   // W column
    int r0 = blockIdx.y * 32;   // W row
    int tx = threadIdx.x, ty = threadIdx.y;

    float sq = 0.0f, mx = 0.0f;
    #pragma unroll
    for (int i = 0; i < 4; i++) {
        float v = W[(size_t)(r0 + ty + i * 8) * KDIM + (c0 + tx)];
        tile[ty + i * 8][tx] = v;
        sq += v * v;
        mx = fmaxf(mx, fabsf(v));
    }
    sqs[ty][tx] = sq;
    mxs[ty][tx] = mx;
    __syncthreads();

    if (ty == 0) {
        float tot = 0.0f, m = 0.0f;
        #pragma unroll
        for (int j = 0; j < 8; j++) { tot += sqs[j][tx]; m = fmaxf(m, mxs[j][tx]); }
        int half = (r0 >= KDIM) ? 1 : 0;
        int o = 2 * (c0 + tx) + half;
        atomicAdd(&g_psq[o], tot);
        atomicMax(&g_wmaxi[o], __float_as_int(m));   // valid: all values >= 0
    }

    #pragma unroll
    for (int i = 0; i < 4; i++) {
        int c = c0 + ty + i * 8;
        int r = r0 + tx;
        g_wb[(size_t)c * NDIM + r] = __float2bfloat16_rn(tile[tx][ty + i * 8]);
    }
}

// ---------------------------------------------------------------------------
// Kernel 3b: quantize protos bf16 -> int8 with per-o scale. 1 block/o.
// ---------------------------------------------------------------------------
__global__ void quant_w_k() {
    int o = blockIdx.x;
    int t = threadIdx.x;
    float inv = 127.0f / __int_as_float(g_wmaxi[o]);

    uint4 raw = *reinterpret_cast<const uint4*>(g_wb + (size_t)o * KDIM + t * 8);
    const __nv_bfloat162* h = reinterpret_cast<const __nv_bfloat162*>(&raw);
    int q[8];
    #pragma unroll
    for (int j = 0; j < 4; j++) {
        float2 f = __bfloat1622float2(h[j]);
        q[2*j]   = __float2int_rn(f.x * inv);
        q[2*j+1] = __float2int_rn(f.y * inv);
    }
    uint2 pk;
    pk.x = (q[0] & 0xFF) | ((q[1] & 0xFF) << 8) | ((q[2] & 0xFF) << 16) | (q[3] << 24);
    pk.y = (q[4] & 0xFF) | ((q[5] & 0xFF) << 8) | ((q[6] & 0xFF) << 16) | (q[7] << 24);
    *reinterpret_cast<uint2*>(g_wq + (size_t)o * KDIM + t * 8) = pk;
}

// ---------------------------------------------------------------------------
// Kernel 4: int8 GEMM.
//   out[b,o] = sx2[b]*sw[o]*acc_i32 - xsq[b] - psq[o] - bias[o]
// BM=128, BN=256, BK=64(s8), 4-stage cp.async, 256 threads (8 warps 2Mx4N),
// warp tile 64x64, register double-buffered fragments, mma.m16n8k32.s8.
// ---------------------------------------------------------------------------
#define BK 64
#define STAGES 4
#define ROWB 80                            // 64 s8 + 16B pad
#define A_BYTES (128 * ROWB)               // 10240
#define B_BYTES (256 * ROWB)               // 20480
#define SLOT_BYTES (A_BYTES + B_BYTES)     // 30720
#define TILE_OFF 2048                      // pbc[256] + swc[256] floats
#define SMEM_TOTAL (TILE_OFF + STAGES * SLOT_BYTES)   // 124928
#define NK2 (KDIM / BK)                    // 32

#define CP16(dst_u32, src_ptr) \
    asm volatile("cp.async.cg.shared.global [%0], [%1], 16;\n" :: "r"(dst_u32), "l"(src_ptr))
#define CP_COMMIT() asm volatile("cp.async.commit_group;\n" ::)
#define CP_WAIT2()  asm volatile("cp.async.wait_group 2;\n" ::)

#define LDSM_X4(r0, r1, r2, r3, addr) \
    asm volatile("ldmatrix.sync.aligned.m8n8.x4.shared.b16 {%0,%1,%2,%3}, [%4];\n" \
                 : "=r"(r0), "=r"(r1), "=r"(r2), "=r"(r3) : "r"(addr))

#define IMMA16832(d, a, b) \
    asm volatile("mma.sync.aligned.m16n8k32.row.col.s32.s8.s8.s32 " \
                 "{%0,%1,%2,%3},{%4,%5,%6,%7},{%8,%9},{%0,%1,%2,%3};\n" \
                 : "+r"(d[0]), "+r"(d[1]), "+r"(d[2]), "+r"(d[3]) \
                 : "r"(a[0]), "r"(a[1]), "r"(a[2]), "r"(a[3]), "r"(b[0]), "r"(b[1]))

#define LDSM_FRAGS(abuf, bbuf, sAs, sBs, ks) do {                              \
    _Pragma("unroll")                                                          \
    for (int mi = 0; mi < 4; ++mi) {                                           \
        uint32_t addr = (sAs) + aoff + (uint32_t)(mi * 16 * ROWB) + (uint32_t)((ks) * 32); \
        LDSM_X4((abuf)[mi][0], (abuf)[mi][1], (abuf)[mi][2], (abuf)[mi][3], addr); \
    }                                                                          \
    _Pragma("unroll")                                                          \
    for (int nj = 0; nj < 4; ++nj) {                                           \
        uint32_t addr = (sBs) + boff + (uint32_t)(nj * 16 * ROWB) + (uint32_t)((ks) * 32); \
        uint32_t r0_, r1_, r2_, r3_;                                           \
        LDSM_X4(r0_, r1_, r2_, r3_, addr);                                     \
        (bbuf)[2 * (nj)][0] = r0_;     (bbuf)[2 * (nj)][1] = r1_;              \
        (bbuf)[2 * (nj) + 1][0] = r2_; (bbuf)[2 * (nj) + 1][1] = r3_;          \
    }                                                                          \
} while (0)

#define MMA_BLOCK(abuf, bbuf) do {                                             \
    _Pragma("unroll")                                                          \
    for (int mi = 0; mi < 4; ++mi)                                             \
        _Pragma("unroll")                                                      \
        for (int ni = 0; ni < 8; ++ni)                                         \
            IMMA16832(acc[mi][ni], (abuf)[mi], (bbuf)[ni]);                    \
} while (0)

__global__ void __launch_bounds__(256, 1) gemm_k(const float* __restrict__ bias,
                                                 float* __restrict__ out) {
    extern __shared__ char smem[];
    const uint32_t sb = (uint32_t)__cvta_generic_to_shared(smem);
    float* pbc = reinterpret_cast<float*>(smem);          // [256] psq+bias
    float* swc = reinterpret_cast<float*>(smem) + 256;    // [256] w scales
    const uint32_t sT = sb + TILE_OFF;

    const int t = threadIdx.x;
    const int bm = blockIdx.y * 128;
    const int bn = blockIdx.x * 256;

    pbc[t] = g_psq[bn + t] + __ldg(&bias[bn + t]);
    swc[t] = __int_as_float(g_wmaxi[bn + t]) * (1.0f / 127.0f);

    const int8_t* gA = g_xq + (size_t)bm * KDIM;
    const int8_t* gB = g_wq + (size_t)bn * KDIM;

    // loader: rows are 64B = 4 chunks. A: 512 chunks (2/thr), B: 1024 (4/thr)
    auto load_slot = [&](int slot, int k0) {
        uint32_t abase = sT + slot * SLOT_BYTES;
        uint32_t bbase = abase + A_BYTES;
        #pragma unroll
        for (int i = 0; i < 2; i++) {
            int c = t + i * 256;
            int row = c >> 2, col = c & 3;
            CP16(abase + (uint32_t)(row * ROWB + col * 16),
                 gA + (size_t)row * KDIM + k0 + col * 16);
        }
        #pragma unroll
        for (int i = 0; i < 4; i++) {
            int c = t + i * 256;
            int row = c >> 2, col = c & 3;
            CP16(bbase + (uint32_t)(row * ROWB + col * 16),
                 gB + (size_t)row * KDIM + k0 + col * 16);
        }
    };

    const int warp = t >> 5, lane = t & 31;
    const int wm = warp & 1;   // 2 x 64 rows
    const int wn = warp >> 1;  // 4 x 64 cols

    const uint32_t aoff = (uint32_t)((wm * 64 + (lane & 15)) * ROWB + (lane >> 4) * 16);
    const uint32_t boff = (uint32_t)((wn * 64 + (lane & 7) + ((lane & 16) >> 1)) * ROWB
                                     + ((lane >> 3) & 1) * 16);

    int acc[4][8][4] = {};
    uint32_t afr[2][4][4];
    uint32_t bfr[2][8][2];

    #pragma unroll
    for (int s = 0; s < STAGES - 1; s++) {
        load_slot(s, s * BK);
        CP_COMMIT();
    }

    CP_WAIT2();
    __syncthreads();

    // preload fragments for (kt=0, ks=0)
    LDSM_FRAGS(afr[0], bfr[0], sT, sT + A_BYTES, 0);

    for (int kt = 0; kt < NK2; ++kt) {
        const uint32_t sAs = sT + (kt % STAGES) * SLOT_BYTES;
        const uint32_t sBs = sAs + A_BYTES;

        LDSM_FRAGS(afr[1], bfr[1], sAs, sBs, 1);
        if (kt + STAGES - 1 < NK2) load_slot((kt + STAGES - 1) % STAGES, (kt + STAGES - 1) * BK);
        CP_COMMIT();

        MMA_BLOCK(afr[0], bfr[0]);

        if (kt + 1 < NK2) {
            CP_WAIT2();
            __syncthreads();
            const uint32_t nAs = sT + ((kt + 1) % STAGES) * SLOT_BYTES;
            LDSM_FRAGS(afr[0], bfr[0], nAs, nAs + A_BYTES, 0);
        }

        MMA_BLOCK(afr[1], bfr[1]);
    }

    // epilogue: out = acc*sx2[row]*sw[col] - xsq[row] - (psq+bias)[col]
    const int gid = lane >> 2, qid = lane & 3;
    #pragma unroll
    for (int mi = 0; mi < 4; ++mi) {
        int row0 = bm + wm * 64 + mi * 16 + gid;
        float xs0 = g_xsq[row0];
        float xs1 = g_xsq[row0 + 8];
        float sr0 = g_sx2[row0];
        float sr1 = g_sx2[row0 + 8];
        #pragma unroll
        for (int ni = 0; ni < 8; ++ni) {
            int lc = wn * 64 + ni * 8 + qid * 2;
            float pb0 = pbc[lc],  pb1 = pbc[lc + 1];
            float sc0 = swc[lc],  sc1 = swc[lc + 1];
            float2 v0, v1;
            v0.x = __int2float_rn(acc[mi][ni][0]) * (sr0 * sc0) - xs0 - pb0;
            v0.y = __int2float_rn(acc[mi][ni][1]) * (sr0 * sc1) - xs0 - pb1;
            v1.x = __int2float_rn(acc[mi][ni][2]) * (sr1 * sc0) - xs1 - pb0;
            v1.y = __int2float_rn(acc[mi][ni][3]) * (sr1 * sc1) - xs1 - pb1;
            *reinterpret_cast<float2*>(out + (size_t)row0 * NDIM + bn + lc) = v0;
            *reinterpret_cast<float2*>(out + (size_t)(row0 + 8) * NDIM + bn + lc) = v1;
        }
    }
}

// ---------------------------------------------------------------------------
extern "C" void kernel_launch(void* const* d_in, const int* in_sizes, int n_in,
                              void* d_out, int out_size) {
    const float* x    = (const float*)d_in[0];
    const float* W    = (const float*)d_in[1];
    const float* bias = (const float*)d_in[2];
    float* out = (float*)d_out;

    cudaFuncSetAttribute(gemm_k, cudaFuncAttributeMaxDynamicSharedMemorySize, SMEM_TOTAL);

    zero_k<<<NDIM / 256, 256>>>();
    pack_x_k<<<BDIM, 256>>>(x);
    pack_w_k<<<dim3(KDIM / 32, NDIM / 32), dim3(32, 8)>>>(W);
    quant_w_k<<<NDIM, 256>>>();
    gemm_k<<<dim3(NDIM / 256, BDIM / 128), 256, SMEM_TOTAL>>>(bias, out);
}

// round 8
// speedup vs baseline: 2.5456x; 2.5456x over previous
#include <cuda_runtime.h>
#include <cuda_fp16.h>
#include <cstdint>

#define BDIM 1024
#define KDIM 2048
#define NDIM 4096

// Scratch (device globals — no allocation allowed)
__device__ __half g_xh[BDIM * KDIM];   // 2*x in fp16 [1024][2048]
__device__ __half g_wh[NDIM * KDIM];   // protos in fp16 [4096][2048]
__device__ float g_xsq[BDIM];
__device__ float g_psq[NDIM];

// ---------------------------------------------------------------------------
// Kernel 1: zero p_sq accumulator
// ---------------------------------------------------------------------------
__global__ void zero_psq_k() {
    int i = blockIdx.x * blockDim.x + threadIdx.x;
    if (i < NDIM) g_psq[i] = 0.0f;
}

// ---------------------------------------------------------------------------
// Kernel 2: pack 2*x -> fp16, x_sq in fp32. 1 block/row, 256 threads.
// ---------------------------------------------------------------------------
__global__ void pack_x_k(const float* __restrict__ x) {
    int row = blockIdx.x;
    int t = threadIdx.x;
    const float4* xr = reinterpret_cast<const float4*>(x + (size_t)row * KDIM);
    float4 v0 = xr[t * 2];
    float4 v1 = xr[t * 2 + 1];
    float s = v0.x*v0.x + v0.y*v0.y + v0.z*v0.z + v0.w*v0.w
            + v1.x*v1.x + v1.y*v1.y + v1.z*v1.z + v1.w*v1.w;

    __half2 o0 = __floats2half2_rn(2.f*v0.x, 2.f*v0.y);
    __half2 o1 = __floats2half2_rn(2.f*v0.z, 2.f*v0.w);
    __half2 o2 = __floats2half2_rn(2.f*v1.x, 2.f*v1.y);
    __half2 o3 = __floats2half2_rn(2.f*v1.z, 2.f*v1.w);
    uint4 pk;
    pk.x = *reinterpret_cast<uint32_t*>(&o0);
    pk.y = *reinterpret_cast<uint32_t*>(&o1);
    pk.z = *reinterpret_cast<uint32_t*>(&o2);
    pk.w = *reinterpret_cast<uint32_t*>(&o3);
    reinterpret_cast<uint4*>(g_xh + (size_t)row * KDIM)[t] = pk;

    #pragma unroll
    for (int off = 16; off; off >>= 1) s += __shfl_xor_sync(0xffffffffu, s, off);
    __shared__ float ws[8];
    if ((t & 31) == 0) ws[t >> 5] = s;
    __syncthreads();
    if (t == 0) {
        float tot = 0.0f;
        #pragma unroll
        for (int j = 0; j < 8; j++) tot += ws[j];
        g_xsq[row] = tot;
    }
}

// ---------------------------------------------------------------------------
// Kernel 3: transpose W [4096,2048] fp32 -> protos fp16 [4096][2048]
// (flat(W^T) == flat(protos)), fused p_sq partial sums.
// ---------------------------------------------------------------------------
__global__ void pack_w_k(const float* __restrict__ W) {
    __shared__ float tile[32][33];
    __shared__ float sqs[8][32];

    int c0 = blockIdx.x * 32;   // W column
    int r0 = blockIdx.y * 32;   // W row
    int tx = threadIdx.x, ty = threadIdx.y;

    float sq = 0.0f;
    #pragma unroll
    for (int i = 0; i < 4; i++) {
        float v = W[(size_t)(r0 + ty + i * 8) * KDIM + (c0 + tx)];
        tile[ty + i * 8][tx] = v;
        sq += v * v;
    }
    sqs[ty][tx] = sq;
    __syncthreads();

    if (ty == 0) {
        float tot = 0.0f;
        #pragma unroll
        for (int j = 0; j < 8; j++) tot += sqs[j][tx];
        int half = (r0 >= KDIM) ? 1 : 0;
        atomicAdd(&g_psq[2 * (c0 + tx) + half], tot);
    }

    #pragma unroll
    for (int i = 0; i < 4; i++) {
        int c = c0 + ty + i * 8;
        int r = r0 + tx;
        g_wh[(size_t)c * NDIM + r] = __float2half_rn(tile[tx][ty + i * 8]);
    }
}

// ---------------------------------------------------------------------------
// Kernel 4: GEMM  out[b,o] = sum_k (2x)h[b,k]*wh[o,k] - xsq[b] - psq[o] - bias[o]
// BM=128, BN=256, BK=32, 4-stage cp.async, 256 threads (8 warps, 2Mx4N),
// warp tile 64x64, register double-buffered fragments, FP16 ACCUMULATION.
// ---------------------------------------------------------------------------
#define BK 32
#define STAGES 4
#define ROWB 80                            // bytes per padded smem row
#define A_BYTES (128 * ROWB)               // 10240
#define B_BYTES (256 * ROWB)               // 20480
#define SLOT_BYTES (A_BYTES + B_BYTES)     // 30720
#define TILE_OFF 1024                      // pbc[256] floats first
#define SMEM_TOTAL (TILE_OFF + STAGES * SLOT_BYTES)   // 123904

#define CP16(dst_u32, src_ptr) \
    asm volatile("cp.async.cg.shared.global [%0], [%1], 16;\n" :: "r"(dst_u32), "l"(src_ptr))
#define CP_COMMIT() asm volatile("cp.async.commit_group;\n" ::)
#define CP_WAIT2()  asm volatile("cp.async.wait_group 2;\n" ::)

#define LDSM_X4(r0, r1, r2, r3, addr) \
    asm volatile("ldmatrix.sync.aligned.m8n8.x4.shared.b16 {%0,%1,%2,%3}, [%4];\n" \
                 : "=r"(r0), "=r"(r1), "=r"(r2), "=r"(r3) : "r"(addr))

// fp16-accumulate HMMA: D,C are 2 packed f16x2 regs
#define MMA16816H(d, a, b) \
    asm volatile("mma.sync.aligned.m16n8k16.row.col.f16.f16.f16.f16 " \
                 "{%0,%1},{%2,%3,%4,%5},{%6,%7},{%0,%1};\n" \
                 : "+r"(d[0]), "+r"(d[1]) \
                 : "r"(a[0]), "r"(a[1]), "r"(a[2]), "r"(a[3]), "r"(b[0]), "r"(b[1]))

#define LDSM_FRAGS(abuf, bbuf, sAs, sBs, ks) do {                              \
    _Pragma("unroll")                                                          \
    for (int mi = 0; mi < 4; ++mi) {                                           \
        uint32_t addr = (sAs) + aoff + (uint32_t)(mi * 16 * ROWB) + (uint32_t)((ks) * 32); \
        LDSM_X4((abuf)[mi][0], (abuf)[mi][1], (abuf)[mi][2], (abuf)[mi][3], addr); \
    }                                                                          \
    _Pragma("unroll")                                                          \
    for (int nj = 0; nj < 4; ++nj) {                                           \
        uint32_t addr = (sBs) + boff + (uint32_t)(nj * 16 * ROWB) + (uint32_t)((ks) * 32); \
        uint32_t r0_, r1_, r2_, r3_;                                           \
        LDSM_X4(r0_, r1_, r2_, r3_, addr);                                     \
        (bbuf)[2 * (nj)][0] = r0_;     (bbuf)[2 * (nj)][1] = r1_;              \
        (bbuf)[2 * (nj) + 1][0] = r2_; (bbuf)[2 * (nj) + 1][1] = r3_;          \
    }                                                                          \
} while (0)

#define MMA_BLOCK(abuf, bbuf) do {                                             \
    _Pragma("unroll")                                                          \
    for (int mi = 0; mi < 4; ++mi)                                             \
        _Pragma("unroll")                                                      \
        for (int ni = 0; ni < 8; ++ni)                                         \
            MMA16816H(acc[mi][ni], (abuf)[mi], (bbuf)[ni]);                    \
} while (0)

__global__ void __launch_bounds__(256, 1) gemm_k(const float* __restrict__ bias,
                                                 float* __restrict__ out) {
    extern __shared__ char smem[];
    const uint32_t sb = (uint32_t)__cvta_generic_to_shared(smem);
    float* pbc = reinterpret_cast<float*>(smem);     // [256] psq+bias
    const uint32_t sT = sb + TILE_OFF;

    const int t = threadIdx.x;
    const int bm = blockIdx.y * 128;
    const int bn = blockIdx.x * 256;

    pbc[t] = g_psq[bn + t] + __ldg(&bias[bn + t]);

    const __half* gA = g_xh + (size_t)bm * KDIM;
    const __half* gB = g_wh + (size_t)bn * KDIM;

    // loader: A 512 chunks (2/thread), B 1024 chunks (4/thread); row=c>>2, col=c&3
    auto load_slot = [&](int slot, int k0) {
        uint32_t abase = sT + slot * SLOT_BYTES;
        uint32_t bbase = abase + A_BYTES;
        #pragma unroll
        for (int i = 0; i < 2; i++) {
            int c = t + i * 256;
            int row = c >> 2, col = c & 3;
            CP16(abase + (uint32_t)(row * ROWB + col * 16),
                 gA + (size_t)row * KDIM + k0 + col * 8);
        }
        #pragma unroll
        for (int i = 0; i < 4; i++) {
            int c = t + i * 256;
            int row = c >> 2, col = c & 3;
            CP16(bbase + (uint32_t)(row * ROWB + col * 16),
                 gB + (size_t)row * KDIM + k0 + col * 8);
        }
    };

    const int warp = t >> 5, lane = t & 31;
    const int wm = warp & 1;   // 2 x 64 rows
    const int wn = warp >> 1;  // 4 x 64 cols

    const uint32_t aoff = (uint32_t)((wm * 64 + (lane & 15)) * ROWB + (lane >> 4) * 16);
    const uint32_t boff = (uint32_t)((wn * 64 + (lane & 7) + ((lane & 16) >> 1)) * ROWB
                                     + ((lane >> 3) & 1) * 16);

    uint32_t acc[4][8][2];
    #pragma unroll
    for (int mi = 0; mi < 4; ++mi)
        #pragma unroll
        for (int ni = 0; ni < 8; ++ni)
            acc[mi][ni][0] = acc[mi][ni][1] = 0u;

    uint32_t afr[2][4][4];
    uint32_t bfr[2][8][2];

    #pragma unroll
    for (int s = 0; s < STAGES - 1; s++) {
        load_slot(s, s * BK);
        CP_COMMIT();
    }

    CP_WAIT2();
    __syncthreads();

    // preload fragments for (kt=0, ks=0)
    LDSM_FRAGS(afr[0], bfr[0], sT, sT + A_BYTES, 0);

    const int NK = KDIM / BK;   // 64
    for (int kt = 0; kt < NK; ++kt) {
        const uint32_t sAs = sT + (kt % STAGES) * SLOT_BYTES;
        const uint32_t sBs = sAs + A_BYTES;

        LDSM_FRAGS(afr[1], bfr[1], sAs, sBs, 1);
        if (kt + STAGES - 1 < NK) load_slot((kt + STAGES - 1) % STAGES, (kt + STAGES - 1) * BK);
        CP_COMMIT();

        MMA_BLOCK(afr[0], bfr[0]);

        if (kt + 1 < NK) {
            CP_WAIT2();
            __syncthreads();
            const uint32_t nAs = sT + ((kt + 1) % STAGES) * SLOT_BYTES;
            LDSM_FRAGS(afr[0], bfr[0], nAs, nAs + A_BYTES, 0);
        }

        MMA_BLOCK(afr[1], bfr[1]);
    }

    // epilogue: out = acc - xsq[row] - (psq+bias)[col]
    const int gid = lane >> 2, qid = lane & 3;
    #pragma unroll
    for (int mi = 0; mi < 4; ++mi) {
        int row0 = bm + wm * 64 + mi * 16 + gid;
        float xs0 = g_xsq[row0];
        float xs1 = g_xsq[row0 + 8];
        #pragma unroll
        for (int ni = 0; ni < 8; ++ni) {
            int lc = wn * 64 + ni * 8 + qid * 2;
            float pb0 = pbc[lc];
            float pb1 = pbc[lc + 1];
            float2 f0 = __half22float2(*reinterpret_cast<__half2*>(&acc[mi][ni][0]));
            float2 f1 = __half22float2(*reinterpret_cast<__half2*>(&acc[mi][ni][1]));
            float2 v0, v1;
            v0.x = f0.x - xs0 - pb0;
            v0.y = f0.y - xs0 - pb1;
            v1.x = f1.x - xs1 - pb0;
            v1.y = f1.y - xs1 - pb1;
            *reinterpret_cast<float2*>(out + (size_t)row0 * NDIM + bn + lc) = v0;
            *reinterpret_cast<float2*>(out + (size_t)(row0 + 8) * NDIM + bn + lc) = v1;
        }
    }
}

// ---------------------------------------------------------------------------
extern "C" void kernel_launch(void* const* d_in, const int* in_sizes, int n_in,
                              void* d_out, int out_size) {
    const float* x    = (const float*)d_in[0];
    const float* W    = (const float*)d_in[1];
    const float* bias = (const float*)d_in[2];
    float* out = (float*)d_out;

    cudaFuncSetAttribute(gemm_k, cudaFuncAttributeMaxDynamicSharedMemorySize, SMEM_TOTAL);

    zero_psq_k<<<NDIM / 256, 256>>>();
    pack_x_k<<<BDIM, 256>>>(x);
    pack_w_k<<<dim3(KDIM / 32, NDIM / 32), dim3(32, 8)>>>(W);
    gemm_k<<<dim3(NDIM / 256, BDIM / 128), 256, SMEM_TOTAL>>>(bias, out);
}

// round 9
// speedup vs baseline: 2.6213x; 1.0297x over previous
#include <cuda_runtime.h>
#include <cuda_fp16.h>
#include <cstdint>

#define BDIM 1024
#define KDIM 2048
#define NDIM 4096

// Scratch (device globals — no allocation allowed)
__device__ __half g_xh[BDIM * KDIM];   // 2*x in fp16 [1024][2048]
__device__ __half g_wh[NDIM * KDIM];   // protos in fp16 (flat(Wt[2048][4096]))
__device__ float g_xsq[BDIM];
__device__ float g_psq[NDIM];

// ---------------------------------------------------------------------------
// Kernel 1: pack 2*x -> fp16, x_sq fp32, AND zero g_psq (runs before pack_w).
// 1 block/row, 256 threads.
// ---------------------------------------------------------------------------
__global__ void pack_x_k(const float* __restrict__ x) {
    int row = blockIdx.x;
    int t = threadIdx.x;

    if (t < 4) g_psq[blockIdx.x * 4 + t] = 0.0f;   // 1024 blocks x 4 = 4096

    const float4* xr = reinterpret_cast<const float4*>(x + (size_t)row * KDIM);
    float4 v0 = xr[t * 2];
    float4 v1 = xr[t * 2 + 1];
    float s = v0.x*v0.x + v0.y*v0.y + v0.z*v0.z + v0.w*v0.w
            + v1.x*v1.x + v1.y*v1.y + v1.z*v1.z + v1.w*v1.w;

    __half2 o0 = __floats2half2_rn(2.f*v0.x, 2.f*v0.y);
    __half2 o1 = __floats2half2_rn(2.f*v0.z, 2.f*v0.w);
    __half2 o2 = __floats2half2_rn(2.f*v1.x, 2.f*v1.y);
    __half2 o3 = __floats2half2_rn(2.f*v1.z, 2.f*v1.w);
    uint4 pk;
    pk.x = *reinterpret_cast<uint32_t*>(&o0);
    pk.y = *reinterpret_cast<uint32_t*>(&o1);
    pk.z = *reinterpret_cast<uint32_t*>(&o2);
    pk.w = *reinterpret_cast<uint32_t*>(&o3);
    reinterpret_cast<uint4*>(g_xh + (size_t)row * KDIM)[t] = pk;

    #pragma unroll
    for (int off = 16; off; off >>= 1) s += __shfl_xor_sync(0xffffffffu, s, off);
    __shared__ float ws[8];
    if ((t & 31) == 0) ws[t >> 5] = s;
    __syncthreads();
    if (t == 0) {
        float tot = 0.0f;
        #pragma unroll
        for (int j = 0; j < 8; j++) tot += ws[j];
        g_xsq[row] = tot;
    }
}

// ---------------------------------------------------------------------------
// Kernel 2: transpose W [4096,2048] fp32 -> Wt fp16 [2048][4096]
// (flat(Wt) == flat(protos[4096][2048])), fused p_sq partial sums.
// 64x64 tiles, 256 threads, float4 loads, 128B-contiguous half stores.
// Grid: (2048/64, 4096/64) = (32, 64).
// ---------------------------------------------------------------------------
__global__ void __launch_bounds__(256) pack_w_k(const float* __restrict__ W) {
    __shared__ float tile[64][65];
    __shared__ float sqp[4][64];

    const int c0 = blockIdx.x * 64;   // W column base
    const int r0 = blockIdx.y * 64;   // W row base
    const int t = threadIdx.x;

    // load: 64 rows x 16 float4 = 1024 float4, 4/thread, coalesced
    #pragma unroll
    for (int i = 0; i < 4; i++) {
        int idx = t + i * 256;
        int row = idx >> 4;           // 0..63
        int c4  = (idx & 15) * 4;     // 0,4,..,60
        float4 v = *reinterpret_cast<const float4*>(
            W + (size_t)(r0 + row) * KDIM + c0 + c4);
        tile[row][c4 + 0] = v.x;
        tile[row][c4 + 1] = v.y;
        tile[row][c4 + 2] = v.z;
        tile[row][c4 + 3] = v.w;
    }
    __syncthreads();

    // store: thread t -> W-column c = t>>2, row segment seg = t&3 (16 rows)
    const int c   = t >> 2;
    const int seg = t & 3;
    __half hv[16];
    float sq = 0.0f;
    #pragma unroll
    for (int j = 0; j < 16; j++) {
        float v = tile[seg * 16 + j][c];
        hv[j] = __float2half_rn(v);
        sq += v * v;
    }
    // 32B store, contiguous 128B per W-column across the 4 segs
    *reinterpret_cast<uint4*>(g_wh + (size_t)(c0 + c) * NDIM + r0 + seg * 16) =
        *reinterpret_cast<uint4*>(hv);
    sqp[seg][c] = sq;
    __syncthreads();

    if (seg == 0) {
        float tot = sqp[0][c] + sqp[1][c] + sqp[2][c] + sqp[3][c];
        int half = (r0 >= KDIM) ? 1 : 0;
        atomicAdd(&g_psq[2 * (c0 + c) + half], tot);
    }
}

// ---------------------------------------------------------------------------
// Kernel 3: GEMM  out[b,o] = sum_k (2x)h[b,k]*wh_flat[o*2048+k] - xsq - psq - bias
// BM=128, BN=256, BK=32, 4-stage cp.async, 256 threads (8 warps, 2Mx4N),
// warp tile 64x64, register double-buffered fragments, fp16 accumulation.
// ---------------------------------------------------------------------------
#define BK 32
#define STAGES 4
#define ROWB 80                            // bytes per padded smem row
#define A_BYTES (128 * ROWB)               // 10240
#define B_BYTES (256 * ROWB)               // 20480
#define SLOT_BYTES (A_BYTES + B_BYTES)     // 30720
#define TILE_OFF 1024                      // pbc[256] floats first
#define SMEM_TOTAL (TILE_OFF + STAGES * SLOT_BYTES)   // 123904

#define CP16(dst_u32, src_ptr) \
    asm volatile("cp.async.cg.shared.global [%0], [%1], 16;\n" :: "r"(dst_u32), "l"(src_ptr))
#define CP_COMMIT() asm volatile("cp.async.commit_group;\n" ::)
#define CP_WAIT2()  asm volatile("cp.async.wait_group 2;\n" ::)

#define LDSM_X4(r0, r1, r2, r3, addr) \
    asm volatile("ldmatrix.sync.aligned.m8n8.x4.shared.b16 {%0,%1,%2,%3}, [%4];\n" \
                 : "=r"(r0), "=r"(r1), "=r"(r2), "=r"(r3) : "r"(addr))

#define MMA16816H(d, a, b) \
    asm volatile("mma.sync.aligned.m16n8k16.row.col.f16.f16.f16.f16 " \
                 "{%0,%1},{%2,%3,%4,%5},{%6,%7},{%0,%1};\n" \
                 : "+r"(d[0]), "+r"(d[1]) \
                 : "r"(a[0]), "r"(a[1]), "r"(a[2]), "r"(a[3]), "r"(b[0]), "r"(b[1]))

#define LDSM_FRAGS(abuf, bbuf, sAs, sBs, ks) do {                              \
    _Pragma("unroll")                                                          \
    for (int mi = 0; mi < 4; ++mi) {                                           \
        uint32_t addr = (sAs) + aoff + (uint32_t)(mi * 16 * ROWB) + (uint32_t)((ks) * 32); \
        LDSM_X4((abuf)[mi][0], (abuf)[mi][1], (abuf)[mi][2], (abuf)[mi][3], addr); \
    }                                                                          \
    _Pragma("unroll")                                                          \
    for (int nj = 0; nj < 4; ++nj) {                                           \
        uint32_t addr = (sBs) + boff + (uint32_t)(nj * 16 * ROWB) + (uint32_t)((ks) * 32); \
        uint32_t r0_, r1_, r2_, r3_;                                           \
        LDSM_X4(r0_, r1_, r2_, r3_, addr);                                     \
        (bbuf)[2 * (nj)][0] = r0_;     (bbuf)[2 * (nj)][1] = r1_;              \
        (bbuf)[2 * (nj) + 1][0] = r2_; (bbuf)[2 * (nj) + 1][1] = r3_;          \
    }                                                                          \
} while (0)

#define MMA_BLOCK(abuf, bbuf) do {                                             \
    _Pragma("unroll")                                                          \
    for (int mi = 0; mi < 4; ++mi)                                             \
        _Pragma("unroll")                                                      \
        for (int ni = 0; ni < 8; ++ni)                                         \
            MMA16816H(acc[mi][ni], (abuf)[mi], (bbuf)[ni]);                    \
} while (0)

__global__ void __launch_bounds__(256, 1) gemm_k(const float* __restrict__ bias,
                                                 float* __restrict__ out) {
    extern __shared__ char smem[];
    const uint32_t sb = (uint32_t)__cvta_generic_to_shared(smem);
    float* pbc = reinterpret_cast<float*>(smem);     // [256] psq+bias
    const uint32_t sT = sb + TILE_OFF;

    const int t = threadIdx.x;
    const int bm = blockIdx.y * 128;
    const int bn = blockIdx.x * 256;

    pbc[t] = g_psq[bn + t] + __ldg(&bias[bn + t]);

    const __half* gA = g_xh + (size_t)bm * KDIM;
    const __half* gB = g_wh + (size_t)bn * KDIM;   // flat(Wt) == protos rows

    auto load_slot = [&](int slot, int k0) {
        uint32_t abase = sT + slot * SLOT_BYTES;
        uint32_t bbase = abase + A_BYTES;
        #pragma unroll
        for (int i = 0; i < 2; i++) {
            int c = t + i * 256;
            int row = c >> 2, col = c & 3;
            CP16(abase + (uint32_t)(row * ROWB + col * 16),
                 gA + (size_t)row * KDIM + k0 + col * 8);
        }
        #pragma unroll
        for (int i = 0; i < 4; i++) {
            int c = t + i * 256;
            int row = c >> 2, col = c & 3;
            CP16(bbase + (uint32_t)(row * ROWB + col * 16),
                 gB + (size_t)row * KDIM + k0 + col * 8);
        }
    };

    const int warp = t >> 5, lane = t & 31;
    const int wm = warp & 1;   // 2 x 64 rows
    const int wn = warp >> 1;  // 4 x 64 cols

    const uint32_t aoff = (uint32_t)((wm * 64 + (lane & 15)) * ROWB + (lane >> 4) * 16);
    const uint32_t boff = (uint32_t)((wn * 64 + (lane & 7) + ((lane & 16) >> 1)) * ROWB
                                     + ((lane >> 3) & 1) * 16);

    uint32_t acc[4][8][2];
    #pragma unroll
    for (int mi = 0; mi < 4; ++mi)
        #pragma unroll
        for (int ni = 0; ni < 8; ++ni)
            acc[mi][ni][0] = acc[mi][ni][1] = 0u;

    uint32_t afr[2][4][4];
    uint32_t bfr[2][8][2];

    #pragma unroll
    for (int s = 0; s < STAGES - 1; s++) {
        load_slot(s, s * BK);
        CP_COMMIT();
    }

    CP_WAIT2();
    __syncthreads();

    LDSM_FRAGS(afr[0], bfr[0], sT, sT + A_BYTES, 0);

    const int NK = KDIM / BK;   // 64
    for (int kt = 0; kt < NK; ++kt) {
        const uint32_t sAs = sT + (kt % STAGES) * SLOT_BYTES;
        const uint32_t sBs = sAs + A_BYTES;

        LDSM_FRAGS(afr[1], bfr[1], sAs, sBs, 1);
        if (kt + STAGES - 1 < NK) load_slot((kt + STAGES - 1) % STAGES, (kt + STAGES - 1) * BK);
        CP_COMMIT();

        MMA_BLOCK(afr[0], bfr[0]);

        if (kt + 1 < NK) {
            CP_WAIT2();
            __syncthreads();
            const uint32_t nAs = sT + ((kt + 1) % STAGES) * SLOT_BYTES;
            LDSM_FRAGS(afr[0], bfr[0], nAs, nAs + A_BYTES, 0);
        }

        MMA_BLOCK(afr[1], bfr[1]);
    }

    // epilogue: out = acc - xsq[row] - (psq+bias)[col]
    const int gid = lane >> 2, qid = lane & 3;
    #pragma unroll
    for (int mi = 0; mi < 4; ++mi) {
        int row0 = bm + wm * 64 + mi * 16 + gid;
        float xs0 = g_xsq[row0];
        float xs1 = g_xsq[row0 + 8];
        #pragma unroll
        for (int ni = 0; ni < 8; ++ni) {
            int lc = wn * 64 + ni * 8 + qid * 2;
            float pb0 = pbc[lc];
            float pb1 = pbc[lc + 1];
            float2 f0 = __half22float2(*reinterpret_cast<__half2*>(&acc[mi][ni][0]));
            float2 f1 = __half22float2(*reinterpret_cast<__half2*>(&acc[mi][ni][1]));
            float2 v0, v1;
            v0.x = f0.x - xs0 - pb0;
            v0.y = f0.y - xs0 - pb1;
            v1.x = f1.x - xs1 - pb0;
            v1.y = f1.y - xs1 - pb1;
            *reinterpret_cast<float2*>(out + (size_t)row0 * NDIM + bn + lc) = v0;
            *reinterpret_cast<float2*>(out + (size_t)(row0 + 8) * NDIM + bn + lc) = v1;
        }
    }
}

// ---------------------------------------------------------------------------
extern "C" void kernel_launch(void* const* d_in, const int* in_sizes, int n_in,
                              void* d_out, int out_size) {
    const float* x    = (const float*)d_in[0];
    const float* W    = (const float*)d_in[1];
    const float* bias = (const float*)d_in[2];
    float* out = (float*)d_out;

    cudaFuncSetAttribute(gemm_k, cudaFuncAttributeMaxDynamicSharedMemorySize, SMEM_TOTAL);

    pack_x_k<<<BDIM, 256>>>(x);                                   // also zeros psq
    pack_w_k<<<dim3(KDIM / 64, NDIM / 64), 256>>>(W);
    gemm_k<<<dim3(NDIM / 256, BDIM / 128), 256, SMEM_TOTAL>>>(bias, out);
}